// round 5
// baseline (speedup 1.0000x reference)
#include <cuda_runtime.h>
#include <cuda_bf16.h>

#define NN 50000
#define EE 1000000
#define IN_DIM 128
#define HID 64
#define NL 4

// ---------------- scratch (static device globals; no allocation) -------------
__device__ float    g_h[NN * HID];     // node features (layer input / output)
__device__ float    g_hp[NN * HID];    // pre-BN layer output
__device__ float    g_A[NN * HID];
__device__ float    g_E[NN * HID];
__device__ unsigned g_Bb[NN * 32];     // Bh rows, bf16x2 packed
__device__ unsigned g_Db[NN * 32];     // Dh rows, bf16x2 packed
__device__ int      g_deg[NN];
__device__ int      g_offs[NN + 1];
__device__ int      g_cursor[NN];
__device__ int      g_csr[EE];         // src of each edge, sorted by dst
__device__ float    g_stats[2 * HID];  // per-channel sum, sumsq

__device__ __forceinline__ unsigned pack_bf16x2(float a, float b) {
    __nv_bfloat162 h = __floats2bfloat162_rn(a, b);
    return *reinterpret_cast<unsigned*>(&h);
}
__device__ __forceinline__ float2 unpack_bf16x2(unsigned u) {
    __nv_bfloat162 h = *reinterpret_cast<__nv_bfloat162*>(&u);
    return __bfloat1622float2(h);
}

// tf32 hi/lo split: x ~= hi + lo, each tf32-representable
__device__ __forceinline__ void tf32_hilo(float x, unsigned& hi, unsigned& lo) {
    unsigned h;
    asm("cvt.rna.tf32.f32 %0, %1;" : "=r"(h) : "f"(x));
    float r = x - __uint_as_float(h);
    unsigned l;
    asm("cvt.rna.tf32.f32 %0, %1;" : "=r"(l) : "f"(r));
    hi = h; lo = l;
}

__device__ __forceinline__ void mma_tf32(float* d, const unsigned* a, const unsigned* b) {
    asm("mma.sync.aligned.m16n8k8.row.col.f32.tf32.tf32.f32 "
        "{%0,%1,%2,%3}, {%4,%5,%6,%7}, {%8,%9}, {%0,%1,%2,%3};"
        : "+f"(d[0]), "+f"(d[1]), "+f"(d[2]), "+f"(d[3])
        : "r"(a[0]), "r"(a[1]), "r"(a[2]), "r"(a[3]), "r"(b[0]), "r"(b[1]));
}

// ---------------- sort edges by dst: hist -> scan -> scatter ------------------
__global__ void k_clear_deg() {
    int i = blockIdx.x * blockDim.x + threadIdx.x;
    if (i < NN) g_deg[i] = 0;
}

__global__ void k_hist(const int* __restrict__ ei) {
    int e = blockIdx.x * blockDim.x + threadIdx.x;
    if (e < EE) {
        int d = ei[EE + e];
        if (d >= 0 && d < NN) atomicAdd(&g_deg[d], 1);
    }
}

__global__ void k_scan() {  // single block, 1024 threads
    __shared__ int wsum[32];
    __shared__ int carry_sh;
    int t = threadIdx.x;
    if (t == 0) carry_sh = 0;
    __syncthreads();
    for (int base = 0; base < NN; base += 1024) {
        int i = base + t;
        int v = (i < NN) ? g_deg[i] : 0;
        int x = v;
        #pragma unroll
        for (int o = 1; o < 32; o <<= 1) {
            int y = __shfl_up_sync(0xffffffffu, x, o);
            if ((t & 31) >= o) x += y;
        }
        if ((t & 31) == 31) wsum[t >> 5] = x;
        __syncthreads();
        if (t < 32) {
            int w = wsum[t];
            #pragma unroll
            for (int o = 1; o < 32; o <<= 1) {
                int y = __shfl_up_sync(0xffffffffu, w, o);
                if (t >= o) w += y;
            }
            wsum[t] = w;
        }
        __syncthreads();
        int incl = x + ((t >= 32) ? wsum[(t >> 5) - 1] : 0);
        int carry = carry_sh;
        if (i < NN) {
            g_offs[i + 1]  = carry + incl;
            g_cursor[i]    = carry + incl - v;
        }
        __syncthreads();
        if (t == 0) carry_sh = carry + wsum[31];
        __syncthreads();
    }
    if (t == 0) g_offs[0] = 0;
}

__global__ void k_scatter(const int* __restrict__ ei) {
    int e = blockIdx.x * blockDim.x + threadIdx.x;
    if (e < EE) {
        int d = ei[EE + e];
        int s = ei[e];
        if (d >= 0 && d < NN) {
            int pos = atomicAdd(&g_cursor[d], 1);
            if (pos >= 0 && pos < EE) g_csr[pos] = s;
        }
    }
}

// ---------------- embed: h = feature @ emb_w + emb_b (SIMT fp32) -------------
__global__ __launch_bounds__(256) void k_embed(const float* __restrict__ X,
                                               const float* __restrict__ W,
                                               const float* __restrict__ bias) {
    __shared__ float Ws[IN_DIM * HID];   // 32KB
    __shared__ float Xs[32 * IN_DIM];    // 16KB
    int t = threadIdx.x;
    int m0 = blockIdx.x * 32;
    for (int idx = t; idx < IN_DIM * HID; idx += 256) Ws[idx] = W[idx];
    for (int idx = t; idx < 32 * IN_DIM; idx += 256) {
        int m = m0 + (idx >> 7);
        Xs[idx] = (m < NN) ? X[m * IN_DIM + (idx & 127)] : 0.f;
    }
    __syncthreads();
    int tx = t & 31, ty = t >> 5;
    int c0 = tx * 2, r0 = ty * 4;
    float acc[4][2];
    #pragma unroll
    for (int i = 0; i < 4; i++) { acc[i][0] = 0.f; acc[i][1] = 0.f; }
    #pragma unroll 8
    for (int k = 0; k < IN_DIM; k++) {
        float2 w = *(const float2*)&Ws[k * HID + c0];
        #pragma unroll
        for (int i = 0; i < 4; i++) {
            float x = Xs[(r0 + i) * IN_DIM + k];
            acc[i][0] += x * w.x;
            acc[i][1] += x * w.y;
        }
    }
    float b0 = bias[c0], b1 = bias[c0 + 1];
    #pragma unroll
    for (int i = 0; i < 4; i++) {
        int m = m0 + r0 + i;
        if (m < NN) {
            g_h[m * HID + c0]     = acc[i][0] + b0;
            g_h[m * HID + c0 + 1] = acc[i][1] + b1;
        }
    }
}

// ---------------- layer linears: tf32 MMA with 3-term compensation -----------
// Block 256 thr (8 warps), 64 rows x 256 cols (A|B|D|E), two 128-col halves.
// Warp w: m-tile (w&3), 64-col strip (w>>2) of current half -> exactly one of
// A/B/D/E per half. smem: Xs 16KB + Ws 32KB = 48KB, XOR-swizzled.
__global__ __launch_bounds__(256) void k_abde(
    const float* __restrict__ Aw, const float* __restrict__ Bw,
    const float* __restrict__ Dw, const float* __restrict__ Ew,
    const float* __restrict__ Ab, const float* __restrict__ Bb,
    const float* __restrict__ Db, const float* __restrict__ Eb) {
    __shared__ float Xs[64 * 64];    // (r,k) at r*64 + (k ^ ((r&3)<<3))
    __shared__ float Ws[64 * 128];   // (k,c) at k*128 + (c ^ ((k&3)<<3))
    int t = threadIdx.x;
    int m0 = blockIdx.x * 64;

    // stage X tile (float4, swizzle preserves 16B alignment)
    for (int idx = t; idx < 64 * 16; idx += 256) {
        int r = idx >> 4, c4 = (idx & 15) * 4;
        float4 v = make_float4(0.f, 0.f, 0.f, 0.f);
        if (m0 + r < NN) v = *(const float4*)&g_h[(m0 + r) * HID + c4];
        *(float4*)&Xs[r * 64 + (c4 ^ ((r & 3) << 3))] = v;
    }

    int lane = t & 31, w = t >> 5;
    int g = lane >> 2, tig = lane & 3;
    int mt = w & 3, nh = w >> 2;        // nh in {0,1}
    int r0 = mt * 16 + g, r1 = r0 + 8;

    #pragma unroll
    for (int half = 0; half < 2; half++) {
        // stage weight half (cols half*128 .. +127 of A|B|D|E concat)
        for (int idx = t; idx < 64 * 128; idx += 256) {
            int k = idx >> 7, c = idx & 127;
            int gc = half * 128 + c;
            int sel = gc >> 6;
            const float* W = (sel == 0) ? Aw : (sel == 1) ? Bw : (sel == 2) ? Dw : Ew;
            Ws[k * 128 + (c ^ ((k & 3) << 3))] = W[k * HID + (gc & 63)];
        }
        __syncthreads();

        float acc[8][4];
        #pragma unroll
        for (int i = 0; i < 8; i++)
            #pragma unroll
            for (int j = 0; j < 4; j++) acc[i][j] = 0.f;

        #pragma unroll
        for (int ks = 0; ks < 8; ks++) {
            int k0 = ks * 8 + tig, k1 = k0 + 4;
            // A fragment (m16k8): a0=(r0,k0) a1=(r1,k0) a2=(r0,k1) a3=(r1,k1)
            float x0 = Xs[r0 * 64 + (k0 ^ ((r0 & 3) << 3))];
            float x1 = Xs[r1 * 64 + (k0 ^ ((r1 & 3) << 3))];
            float x2 = Xs[r0 * 64 + (k1 ^ ((r0 & 3) << 3))];
            float x3 = Xs[r1 * 64 + (k1 ^ ((r1 & 3) << 3))];
            unsigned ah[4], al[4];
            tf32_hilo(x0, ah[0], al[0]);
            tf32_hilo(x1, ah[1], al[1]);
            tf32_hilo(x2, ah[2], al[2]);
            tf32_hilo(x3, ah[3], al[3]);
            #pragma unroll
            for (int nt = 0; nt < 8; nt++) {
                int c = nh * 64 + nt * 8 + g;
                float w0 = Ws[k0 * 128 + (c ^ ((k0 & 3) << 3))];
                float w1 = Ws[k1 * 128 + (c ^ ((k1 & 3) << 3))];
                unsigned bh[2], bl[2];
                tf32_hilo(w0, bh[0], bl[0]);
                tf32_hilo(w1, bh[1], bl[1]);
                mma_tf32(acc[nt], ah, bh);
                mma_tf32(acc[nt], al, bh);
                mma_tf32(acc[nt], ah, bl);
            }
        }

        // store: warp's 64 cols = one matrix. sel = half*2 + nh
        int sel = half * 2 + nh;
        const float* bp = (sel == 0) ? Ab : (sel == 1) ? Bb : (sel == 2) ? Db : Eb;
        int mra = m0 + mt * 16 + g, mrb = mra + 8;
        if (sel == 0 || sel == 3) {
            float* Y = (sel == 0) ? g_A : g_E;
            #pragma unroll
            for (int nt = 0; nt < 8; nt++) {
                int cc = nt * 8 + 2 * tig;
                float b0v = bp[cc], b1v = bp[cc + 1];
                if (mra < NN) {
                    float2 v = make_float2(acc[nt][0] + b0v, acc[nt][1] + b1v);
                    *(float2*)&Y[mra * HID + cc] = v;
                }
                if (mrb < NN) {
                    float2 v = make_float2(acc[nt][2] + b0v, acc[nt][3] + b1v);
                    *(float2*)&Y[mrb * HID + cc] = v;
                }
            }
        } else {
            unsigned* Y = (sel == 1) ? g_Bb : g_Db;
            #pragma unroll
            for (int nt = 0; nt < 8; nt++) {
                int cc = nt * 8 + 2 * tig;
                float b0v = bp[cc], b1v = bp[cc + 1];
                int wc = nt * 4 + tig;
                if (mra < NN) Y[mra * 32 + wc] = pack_bf16x2(acc[nt][0] + b0v, acc[nt][1] + b1v);
                if (mrb < NN) Y[mrb * 32 + wc] = pack_bf16x2(acc[nt][2] + b0v, acc[nt][3] + b1v);
            }
        }
        __syncthreads();   // before Ws reuse
    }
}

// ---------------- edge aggregation + fused BN stats ---------------------------
// 8 warps/block, each warp handles 4 consecutive nodes. Per-block channel
// reduction -> 128 atomics/block into g_stats.
__global__ __launch_bounds__(256) void k_agg() {
    __shared__ float red_s[8][64], red_q[8][64];
    int w = threadIdx.x >> 5, lane = threadIdx.x & 31;
    int base = (blockIdx.x * 8 + w) * 4;
    float sx = 0.f, sy = 0.f, qx = 0.f, qy = 0.f;
    #pragma unroll 1
    for (int i = 0; i < 4; i++) {
        int gw = base + i;
        if (gw >= NN) break;
        int s0 = g_offs[gw], s1 = g_offs[gw + 1];
        int off = gw * HID + lane * 2;
        float2 el = *(const float2*)&g_E[off];
        float nx = 0.f, ny = 0.f, dx = 0.f, dy = 0.f;
        int k = s0;
        for (; k + 1 < s1; k += 2) {
            int sa = g_csr[k], sb = g_csr[k + 1];
            unsigned ua_d = g_Db[sa * 32 + lane];
            unsigned ua_b = g_Bb[sa * 32 + lane];
            unsigned ub_d = g_Db[sb * 32 + lane];
            unsigned ub_b = g_Bb[sb * 32 + lane];
            float2 da = unpack_bf16x2(ua_d), ba = unpack_bf16x2(ua_b);
            float2 db = unpack_bf16x2(ub_d), bb = unpack_bf16x2(ub_b);
            float s0x = 1.f / (1.f + __expf(-(da.x + el.x)));
            float s0y = 1.f / (1.f + __expf(-(da.y + el.y)));
            float s1x = 1.f / (1.f + __expf(-(db.x + el.x)));
            float s1y = 1.f / (1.f + __expf(-(db.y + el.y)));
            nx += s0x * ba.x + s1x * bb.x;
            ny += s0y * ba.y + s1y * bb.y;
            dx += s0x + s1x;
            dy += s0y + s1y;
        }
        if (k < s1) {
            int sa = g_csr[k];
            float2 da = unpack_bf16x2(g_Db[sa * 32 + lane]);
            float2 ba = unpack_bf16x2(g_Bb[sa * 32 + lane]);
            float ssx = 1.f / (1.f + __expf(-(da.x + el.x)));
            float ssy = 1.f / (1.f + __expf(-(da.y + el.y)));
            nx += ssx * ba.x; ny += ssy * ba.y;
            dx += ssx;        dy += ssy;
        }
        float2 aa = *(const float2*)&g_A[off];
        float ox = aa.x + nx / (dx + 1e-6f);
        float oy = aa.y + ny / (dy + 1e-6f);
        float2 o = make_float2(ox, oy);
        *(float2*)&g_hp[off] = o;
        sx += ox; sy += oy; qx += ox * ox; qy += oy * oy;
    }
    red_s[w][lane * 2] = sx;  red_s[w][lane * 2 + 1] = sy;
    red_q[w][lane * 2] = qx;  red_q[w][lane * 2 + 1] = qy;
    __syncthreads();
    int t = threadIdx.x;
    if (t < 64) {
        float s = 0.f, q = 0.f;
        #pragma unroll
        for (int ww = 0; ww < 8; ww++) { s += red_s[ww][t]; q += red_q[ww][t]; }
        atomicAdd(&g_stats[t], s);
        atomicAdd(&g_stats[HID + t], q);
    }
}

// ---------------- BN/ReLU/residual --------------------------------------------
__global__ void k_clear_stats() {
    int t = threadIdx.x;
    if (t < 2 * HID) g_stats[t] = 0.f;
}

__global__ __launch_bounds__(256) void k_bn(const float* __restrict__ gamma,
                                            const float* __restrict__ beta,
                                            float* __restrict__ out,
                                            int write_out) {
    int idx = blockIdx.x * blockDim.x + threadIdx.x;
    if (idx >= NN * HID) return;
    int c = idx & 63;
    const float invN = 1.f / (float)NN;
    float mu  = g_stats[c] * invN;
    float var = g_stats[HID + c] * invN - mu * mu;
    float xn = (g_hp[idx] - mu) * rsqrtf(var + 1e-5f);
    float v = gamma[c] * xn + beta[c];
    v = fmaxf(v, 0.f);
    float r = g_h[idx] + v;
    g_h[idx] = r;
    if (write_out) out[idx] = r;
}

// ---------------- launch ------------------------------------------------------
extern "C" void kernel_launch(void* const* d_in, const int* in_sizes, int n_in,
                              void* d_out, int out_size) {
    const float* feature = (const float*)d_in[0];
    const int*   ei      = (const int*)d_in[1];     // int32 (JAX x64 disabled)
    const float* emb_w   = (const float*)d_in[2];
    const float* emb_b   = (const float*)d_in[3];
    const float* Aw      = (const float*)d_in[4];
    const float* Ab      = (const float*)d_in[5];
    const float* Bw      = (const float*)d_in[6];
    const float* Bb      = (const float*)d_in[7];
    const float* Dw      = (const float*)d_in[8];
    const float* Db      = (const float*)d_in[9];
    const float* Ew      = (const float*)d_in[10];
    const float* Eb      = (const float*)d_in[11];
    const float* gamma   = (const float*)d_in[12];
    const float* beta    = (const float*)d_in[13];
    float* out = (float*)d_out;

    k_clear_deg<<<(NN + 255) / 256, 256>>>();
    k_hist<<<(EE + 255) / 256, 256>>>(ei);
    k_scan<<<1, 1024>>>();
    k_scatter<<<(EE + 255) / 256, 256>>>(ei);

    k_embed<<<(NN + 31) / 32, 256>>>(feature, emb_w, emb_b);

    for (int l = 0; l < NL; l++) {
        k_abde<<<(NN + 63) / 64, 256>>>(
            Aw + l * HID * HID, Bw + l * HID * HID,
            Dw + l * HID * HID, Ew + l * HID * HID,
            Ab + l * HID, Bb + l * HID, Db + l * HID, Eb + l * HID);
        k_clear_stats<<<1, 128>>>();
        k_agg<<<(NN + 31) / 32, 256>>>();
        k_bn<<<(NN * HID + 255) / 256, 256>>>(gamma + l * HID, beta + l * HID,
                                              out, (l == NL - 1) ? 1 : 0);
    }
}